// round 2
// baseline (speedup 1.0000x reference)
#include <cuda_runtime.h>
#include <math.h>

#define LATENT 2048
#define OBS    1024
#define CTRL   512
#define SEQ    4096
#define NCTA   128
#define RPC    16        // latent rows per CTA  (NCTA*RPC == LATENT)
#define NTHR   256

// ---------------- persistent device scratch (no allocations allowed) ----------------
__device__ __align__(16) float g_M  [(size_t)LATENT*LATENT]; // Wout^T Wout
__device__ __align__(16) float g_Gt [(size_t)SEQ*LATENT];    // (Wout^T x_t)   [t][l]
__device__ __align__(16) float g_Ut [(size_t)SEQ*LATENT];    // (Win tanh(u_t))[t][l]
__device__ __align__(16) float g_zpt[(size_t)SEQ*LATENT];    // z_projs (drive)[t][l]
__device__ __align__(16) float g_fz [2][LATENT];             // double-buffered tanh(z)
__device__ unsigned g_flag[NCTA];                            // per-CTA epoch flags

// ---------------- acquire/release helpers ----------------
__device__ __forceinline__ unsigned ld_acq(const unsigned* p) {
  unsigned v;
  asm volatile("ld.acquire.gpu.global.u32 %0, [%1];" : "=r"(v) : "l"(p) : "memory");
  return v;
}
__device__ __forceinline__ void st_rel(unsigned* p, unsigned v) {
  asm volatile("st.release.gpu.global.u32 [%0], %1;" :: "l"(p), "r"(v) : "memory");
}

// ---------------- generic tiled fp32 GEMM ----------------
// C[Md x Nd] row-major, C[m][n] = sum_k a(k,m)*b(k,n)
//   a(k,m) = TA ? A[m*Kd + k] : A[k*Md + m]    (optionally tanh)
//   b(k,n) = TB ? B[n*Kd + k] : B[k*Nd + n]    (optionally tanh)
// RESET: block (0,0) additionally zeroes the epoch flags (replay-safety).
template<bool TA, bool TB, bool TANHA, bool TANHB, bool RESET>
__global__ void gemm_kernel(const float* __restrict__ A, const float* __restrict__ B,
                            float* __restrict__ C, int Md, int Nd, int Kd)
{
  if (RESET && blockIdx.x == 0 && blockIdx.y == 0 && threadIdx.x < NCTA)
    g_flag[threadIdx.x] = 0;

  __shared__ float As[16][68];
  __shared__ float Bs[16][68];
  const int tx = threadIdx.x & 15;
  const int ty = threadIdx.x >> 4;
  const int m0 = blockIdx.y * 64;
  const int n0 = blockIdx.x * 64;
  float acc[4][4];
  #pragma unroll
  for (int i = 0; i < 4; i++)
    #pragma unroll
    for (int j = 0; j < 4; j++) acc[i][j] = 0.f;

  for (int k0 = 0; k0 < Kd; k0 += 16) {
    #pragma unroll
    for (int l = 0; l < 4; l++) {
      int i = threadIdx.x + l * 256;
      int kk, mm;
      if (TA) { kk = i & 15; mm = i >> 4; } else { kk = i >> 6; mm = i & 63; }
      float v = TA ? A[(size_t)(m0 + mm) * Kd + (k0 + kk)]
                   : A[(size_t)(k0 + kk) * Md + (m0 + mm)];
      if (TANHA) v = tanhf(v);
      As[kk][mm] = v;
      int kk2, nn;
      if (TB) { kk2 = i & 15; nn = i >> 4; } else { kk2 = i >> 6; nn = i & 63; }
      float w = TB ? B[(size_t)(n0 + nn) * Kd + (k0 + kk2)]
                   : B[(size_t)(k0 + kk2) * Nd + (n0 + nn)];
      if (TANHB) w = tanhf(w);
      Bs[kk2][nn] = w;
    }
    __syncthreads();
    #pragma unroll
    for (int kk = 0; kk < 16; kk++) {
      float a[4], bb[4];
      #pragma unroll
      for (int i = 0; i < 4; i++) a[i]  = As[kk][ty * 4 + i];
      #pragma unroll
      for (int j = 0; j < 4; j++) bb[j] = Bs[kk][tx * 4 + j];
      #pragma unroll
      for (int i = 0; i < 4; i++)
        #pragma unroll
        for (int j = 0; j < 4; j++)
          acc[i][j] += a[i] * bb[j];
    }
    __syncthreads();
  }
  #pragma unroll
  for (int i = 0; i < 4; i++)
    #pragma unroll
    for (int j = 0; j < 4; j++)
      C[(size_t)(m0 + ty * 4 + i) * Nd + (n0 + tx * 4 + j)] = acc[i][j];
}

// ---------------- persistent sequential kernel ----------------
__device__ __forceinline__ float warp_sum(float v) {
  #pragma unroll
  for (int s = 16; s; s >>= 1) v += __shfl_xor_sync(0xffffffffu, v, s);
  return v;
}

#define SEQ_SMEM ((RPC*LATENT + LATENT + 3*RPC) * 4)  // 139456 bytes

__global__ void __launch_bounds__(NTHR, 1)
seq_kernel(const float* __restrict__ Wr,
           const int* __restrict__ p_it, const float* __restrict__ p_lr,
           float* __restrict__ zs_out)
{
  extern __shared__ float sm[];
  float* Ms  = sm;                    // RPC*LATENT : this CTA's slice of M
  float* fzs = Ms + RPC * LATENT;     // LATENT     : full tanh(z) vector
  float* zl  = fzs + LATENT;          // RPC        : local z rows
  float* dr  = zl + RPC;              // RPC        : local drive rows
  float* gl  = dr + RPC;              // RPC        : local g rows

  const int b    = blockIdx.x;
  const int tid  = threadIdx.x;
  const int w    = tid >> 5, lane = tid & 31;
  const int r0   = 2 * w, r1 = r0 + 1;   // 8 warps x 2 rows = 16 rows
  const int rowb = b * RPC;

  // stage M slice into SMEM once (persists whole kernel)
  {
    const float4* src = (const float4*)(g_M + (size_t)rowb * LATENT);
    float4* dst = (float4*)Ms;
    #pragma unroll 4
    for (int i = tid; i < RPC * LATENT / 4; i += NTHR) dst[i] = src[i];
  }
  // initial fz(z0) = 0, local z = 0
  for (int i = tid; i < LATENT; i += NTHR) fzs[i] = 0.f;
  if (tid < RPC) zl[tid] = 0.f;

  int n_it = p_it[0];
  if (n_it <= 0 || n_it > 1000000) n_it = (int)(((const long long*)p_it)[0]);
  float lr = p_lr[0];
  if (!(lr > 1e-8f && lr < 16.f)) lr = (float)(((const double*)p_lr)[0]);

  unsigned ec = 0;     // last consumed fz epoch (0 = initial zeros)
  __syncthreads();

  for (int t = 0; t < SEQ; t++) {
    if (tid < RPC) gl[tid] = g_Gt[(size_t)t * LATENT + rowb + tid];
    __syncthreads();

    // drive = Wr @ fz + Win tanh(u)   (Wr streamed from L2)
    {
      const float4* a0p = (const float4*)(Wr + (size_t)(rowb + r0) * LATENT);
      const float4* a1p = (const float4*)(Wr + (size_t)(rowb + r1) * LATENT);
      const float4* f4  = (const float4*)fzs;
      float s0 = 0.f, s1 = 0.f;
      #pragma unroll 4
      for (int j = lane; j < LATENT / 4; j += 32) {
        float4 f  = f4[j];
        float4 x0 = __ldg(a0p + j);
        float4 x1 = __ldg(a1p + j);
        s0 += x0.x * f.x + x0.y * f.y + x0.z * f.z + x0.w * f.w;
        s1 += x1.x * f.x + x1.y * f.y + x1.z * f.z + x1.w * f.w;
      }
      s0 = warp_sum(s0); s1 = warp_sum(s1);
      if (lane == 0) {
        dr[r0] = s0 + g_Ut[(size_t)t * LATENT + rowb + r0];
        dr[r1] = s1 + g_Ut[(size_t)t * LATENT + rowb + r1];
      }
    }
    // no sync needed: dr/zl/fzs consumers below are same-thread or unchanged

    // inference iterations: z -= lr * ((z - drive) - (1-fz^2)*(g - M fz))
    for (int k = 0; k < n_it; k++) {
      const float4* m0p = (const float4*)(Ms + r0 * LATENT);
      const float4* m1p = (const float4*)(Ms + r1 * LATENT);
      const float4* f4  = (const float4*)fzs;
      float s0 = 0.f, s1 = 0.f;
      #pragma unroll 4
      for (int j = lane; j < LATENT / 4; j += 32) {
        float4 f  = f4[j];
        float4 x0 = m0p[j];
        float4 x1 = m1p[j];
        s0 += x0.x * f.x + x0.y * f.y + x0.z * f.z + x0.w * f.w;
        s1 += x1.x * f.x + x1.y * f.y + x1.z * f.z + x1.w * f.w;
      }
      s0 = warp_sum(s0); s1 = warp_sum(s1);
      const int wp = (int)((ec + 1) & 1);   // write-buffer parity
      if (lane == 0) {
        float z0 = zl[r0], f0 = fzs[rowb + r0];
        float d0 = (z0 - dr[r0]) - (1.f - f0 * f0) * (gl[r0] - s0);
        z0 -= lr * d0; zl[r0] = z0;
        g_fz[wp][rowb + r0] = tanhf(z0);
        float z1 = zl[r1], f1 = fzs[rowb + r1];
        float d1 = (z1 - dr[r1]) - (1.f - f1 * f1) * (gl[r1] - s1);
        z1 -= lr * d1; zl[r1] = z1;
        g_fz[wp][rowb + r1] = tanhf(z1);
      }
      __syncthreads();                       // all warps' fz stores issued
      if (tid == 0) st_rel(&g_flag[b], ec + 1);  // release: publish epoch
      ec++;
      // ---- fused wait + reload: each of threads 0..127 owns one CTA's chunk ----
      if (!(t == SEQ - 1 && k == n_it - 1)) {
        if (tid < NCTA) {
          while (ld_acq(&g_flag[tid]) < ec) { }
          const float4* s = (const float4*)(g_fz[ec & 1] + tid * RPC);
          float4* d4 = (float4*)(fzs + tid * RPC);
          d4[0] = __ldcg(s + 0);
          d4[1] = __ldcg(s + 1);
          d4[2] = __ldcg(s + 2);
          d4[3] = __ldcg(s + 3);
        }
        __syncthreads();
      }
    }

    // outputs: zs[:,t] (row-major LATENT x SEQ) and z_projs (drive) as [t][l]
    if (tid < RPC) {
      zs_out[(size_t)(rowb + tid) * SEQ + t] = zl[tid];
      g_zpt[(size_t)t * LATENT + rowb + tid] = dr[tid];
    }
  }
}

// ---------------- launch ----------------
extern "C" void kernel_launch(void* const* d_in, const int* in_sizes, int n_in,
                              void* d_out, int out_size)
{
  const float* inputs   = (const float*)d_in[0];  // (OBS,  SEQ)
  const float* controls = (const float*)d_in[1];  // (CTRL, SEQ)
  const float* Wr       = (const float*)d_in[2];  // (LATENT, LATENT)
  const float* Win      = (const float*)d_in[3];  // (LATENT, CTRL)
  const float* Wout     = (const float*)d_in[4];  // (OBS, LATENT)
  const int*   p_it     = (const int*)d_in[5];
  const float* p_lr     = (const float*)d_in[6];

  float* zs   = (float*)d_out;                       // (LATENT, SEQ)
  float* pred = zs + (size_t)LATENT * SEQ;           // (OBS, SEQ)

  float *pM, *pGt, *pUt, *pZpt;
  cudaGetSymbolAddress((void**)&pM,   g_M);
  cudaGetSymbolAddress((void**)&pGt,  g_Gt);
  cudaGetSymbolAddress((void**)&pUt,  g_Ut);
  cudaGetSymbolAddress((void**)&pZpt, g_zpt);

  cudaFuncSetAttribute(seq_kernel, cudaFuncAttributeMaxDynamicSharedMemorySize, SEQ_SMEM);

  dim3 thr(256);
  // M = Wout^T Wout (+ flag reset in block 0)
  gemm_kernel<false,false,false,false,true><<<dim3(LATENT/64, LATENT/64), thr>>>(Wout, Wout, pM, LATENT, LATENT, OBS);
  // Gt[t][l] = sum_i inputs[i][t] * Wout[i][l]
  gemm_kernel<false,false,false,false,false><<<dim3(LATENT/64, SEQ/64), thr>>>(inputs, Wout, pGt, SEQ, LATENT, OBS);
  // Ut[t][l] = sum_c tanh(controls[c][t]) * Win[l][c]
  gemm_kernel<false,true,true,false,false><<<dim3(LATENT/64, SEQ/64), thr>>>(controls, Win, pUt, SEQ, LATENT, CTRL);

  seq_kernel<<<NCTA, NTHR, SEQ_SMEM>>>(Wr, p_it, p_lr, zs);

  // pred[i][t] = sum_l Wout[i][l] * tanh(zpt[t][l])
  gemm_kernel<true,true,false,true,false><<<dim3(SEQ/64, OBS/64), thr>>>(Wout, pZpt, pred, OBS, SEQ, LATENT);
}

// round 3
// speedup vs baseline: 2.5732x; 2.5732x over previous
#include <cuda_runtime.h>
#include <math.h>

#define LATENT 2048
#define OBS    1024
#define CTRL   512
#define SEQ    4096
#define NCTA   128
#define RPC    16        // latent rows per CTA  (NCTA*RPC == LATENT)
#define NTHR   256

// ---------------- persistent device scratch (no allocations allowed) ----------------
__device__ __align__(16) float g_M  [(size_t)LATENT*LATENT]; // Wout^T Wout
__device__ __align__(16) float g_Gt [(size_t)SEQ*LATENT];    // (Wout^T x_t)   [t][l]
__device__ __align__(16) float g_Ut [(size_t)SEQ*LATENT];    // (Win tanh(u_t))[t][l]
__device__ __align__(16) float g_zpt[(size_t)SEQ*LATENT];    // z_projs (drive)[t][l]
__device__ __align__(16) float g_fz [2][LATENT];             // double-buffered tanh(z)
__device__ unsigned g_bar;                                   // central epoch counter

// ---------------- generic tiled fp32 GEMM ----------------
// C[Md x Nd] row-major, C[m][n] = sum_k a(k,m)*b(k,n)
//   a(k,m) = TA ? A[m*Kd + k] : A[k*Md + m]    (optionally tanh)
//   b(k,n) = TB ? B[n*Kd + k] : B[k*Nd + n]    (optionally tanh)
// RESET: block (0,0) zeroes the barrier counter (graph-replay safety).
template<bool TA, bool TB, bool TANHA, bool TANHB, bool RESET>
__global__ void gemm_kernel(const float* __restrict__ A, const float* __restrict__ B,
                            float* __restrict__ C, int Md, int Nd, int Kd)
{
  if (RESET && blockIdx.x == 0 && blockIdx.y == 0 && threadIdx.x == 0)
    g_bar = 0u;

  __shared__ float As[16][68];
  __shared__ float Bs[16][68];
  const int tx = threadIdx.x & 15;
  const int ty = threadIdx.x >> 4;
  const int m0 = blockIdx.y * 64;
  const int n0 = blockIdx.x * 64;
  float acc[4][4];
  #pragma unroll
  for (int i = 0; i < 4; i++)
    #pragma unroll
    for (int j = 0; j < 4; j++) acc[i][j] = 0.f;

  for (int k0 = 0; k0 < Kd; k0 += 16) {
    #pragma unroll
    for (int l = 0; l < 4; l++) {
      int i = threadIdx.x + l * 256;
      int kk, mm;
      if (TA) { kk = i & 15; mm = i >> 4; } else { kk = i >> 6; mm = i & 63; }
      float v = TA ? A[(size_t)(m0 + mm) * Kd + (k0 + kk)]
                   : A[(size_t)(k0 + kk) * Md + (m0 + mm)];
      if (TANHA) v = tanhf(v);
      As[kk][mm] = v;
      int kk2, nn;
      if (TB) { kk2 = i & 15; nn = i >> 4; } else { kk2 = i >> 6; nn = i & 63; }
      float w = TB ? B[(size_t)(n0 + nn) * Kd + (k0 + kk2)]
                   : B[(size_t)(k0 + kk2) * Nd + (n0 + nn)];
      if (TANHB) w = tanhf(w);
      Bs[kk2][nn] = w;
    }
    __syncthreads();
    #pragma unroll
    for (int kk = 0; kk < 16; kk++) {
      float a[4], bb[4];
      #pragma unroll
      for (int i = 0; i < 4; i++) a[i]  = As[kk][ty * 4 + i];
      #pragma unroll
      for (int j = 0; j < 4; j++) bb[j] = Bs[kk][tx * 4 + j];
      #pragma unroll
      for (int i = 0; i < 4; i++)
        #pragma unroll
        for (int j = 0; j < 4; j++)
          acc[i][j] += a[i] * bb[j];
    }
    __syncthreads();
  }
  #pragma unroll
  for (int i = 0; i < 4; i++)
    #pragma unroll
    for (int j = 0; j < 4; j++)
      C[(size_t)(m0 + ty * 4 + i) * Nd + (n0 + tx * 4 + j)] = acc[i][j];
}

// ---------------- persistent sequential kernel ----------------
// 4-way butterfly reduce over 32 lanes (all lanes end with full sums)
__device__ __forceinline__ void bfly4(float& a0, float& a1, float& a2, float& a3) {
  #pragma unroll
  for (int s = 16; s; s >>= 1) {
    a0 += __shfl_xor_sync(0xffffffffu, a0, s);
    a1 += __shfl_xor_sync(0xffffffffu, a1, s);
    a2 += __shfl_xor_sync(0xffffffffu, a2, s);
    a3 += __shfl_xor_sync(0xffffffffu, a3, s);
  }
}

__device__ __forceinline__ float dot4(float4 a, float4 b) {
  return a.x * b.x + a.y * b.y + a.z * b.z + a.w * b.w;
}

#define SEQ_SMEM ((32768 + 2048 + 32 + 32 + 4*16) * 4)   // 139776 bytes

__global__ void __launch_bounds__(NTHR, 1)
seq_kernel(const float* __restrict__ Wr,
           const int* __restrict__ p_it, const float* __restrict__ p_lr,
           float* __restrict__ zs_out)
{
  extern __shared__ float sm[];
  float* Ms     = sm;               // 16 x 2048 : this CTA's slice of M
  float* fzs    = Ms + 32768;       // 2048      : full tanh(z)
  float* part_m = fzs + 2048;       // 32        : [h*16 + row] partials (M pass)
  float* part_w = part_m + 32;      // 32        : partials (Wr pass)
  float* dr     = part_w + 32;      // 16 drive, 16 g, 16 u, 16 z
  float* gl     = dr + 16;
  float* ul     = gl + 16;
  float* zl     = ul + 16;

  const int b    = blockIdx.x;
  const int tid  = threadIdx.x;
  const int w    = tid >> 5, lane = tid & 31;
  const int g    = w >> 1;          // row group: rows 4g..4g+3
  const int h    = w & 1;           // K half: [1024h, 1024h+1024)
  const int rowb = b * RPC;

  // stage M slice into SMEM once
  {
    const float4* src = (const float4*)(g_M + (size_t)rowb * LATENT);
    float4* dst = (float4*)Ms;
    #pragma unroll 4
    for (int i = tid; i < RPC * LATENT / 4; i += NTHR) dst[i] = src[i];
  }
  for (int i = tid; i < LATENT; i += NTHR) fzs[i] = 0.f;
  if (tid < RPC) zl[tid] = 0.f;

  int n_it = p_it[0];
  if (n_it <= 0 || n_it > 1000000) n_it = (int)(((const long long*)p_it)[0]);
  float lr = p_lr[0];
  if (!(lr > 1e-8f && lr < 16.f)) lr = (float)(((const double*)p_lr)[0]);

  // per-warp base pointers (float4 units; row stride = 512 float4)
  const float4* fz4  = (const float4*)fzs + h * 256;
  const float4* Ms4  = (const float4*)Ms + (4 * g) * 512 + h * 256;
  const float4* Wr4  = (const float4*)Wr + ((size_t)(rowb + 4 * g)) * 512 + h * 256;

  unsigned ec = 0;                  // completed epoch count
  __syncthreads();

  for (int t = 0; t < SEQ; t++) {
    if (tid < RPC) {
      gl[tid] = g_Gt[(size_t)t * LATENT + rowb + tid];
      ul[tid] = g_Ut[(size_t)t * LATENT + rowb + tid];
    }

    for (int k = 0; k < n_it; k++) {
      const bool first = (k == 0);
      // ---- matvec: acc_m = M[4g..4g+3][Khalf] . fz ; (k==0) also Wr rows ----
      float a0 = 0.f, a1 = 0.f, a2 = 0.f, a3 = 0.f;
      float w0 = 0.f, w1 = 0.f, w2 = 0.f, w3 = 0.f;
      if (first) {
        #pragma unroll
        for (int i = 0; i < 8; i++) {
          const int o = i * 32 + lane;
          float4 f  = fz4[o];
          a0 += dot4(Ms4[o], f);
          a1 += dot4(Ms4[o + 512], f);
          a2 += dot4(Ms4[o + 1024], f);
          a3 += dot4(Ms4[o + 1536], f);
          w0 += dot4(__ldg(Wr4 + o), f);
          w1 += dot4(__ldg(Wr4 + o + 512), f);
          w2 += dot4(__ldg(Wr4 + o + 1024), f);
          w3 += dot4(__ldg(Wr4 + o + 1536), f);
        }
        bfly4(w0, w1, w2, w3);
        if (lane < 4) {
          float v = (lane == 0) ? w0 : (lane == 1) ? w1 : (lane == 2) ? w2 : w3;
          part_w[h * 16 + 4 * g + lane] = v;
        }
      } else {
        #pragma unroll
        for (int i = 0; i < 8; i++) {
          const int o = i * 32 + lane;
          float4 f  = fz4[o];
          a0 += dot4(Ms4[o], f);
          a1 += dot4(Ms4[o + 512], f);
          a2 += dot4(Ms4[o + 1024], f);
          a3 += dot4(Ms4[o + 1536], f);
        }
      }
      bfly4(a0, a1, a2, a3);
      if (lane < 4) {
        float v = (lane == 0) ? a0 : (lane == 1) ? a1 : (lane == 2) ? a2 : a3;
        part_m[h * 16 + 4 * g + lane] = v;
      }
      __syncthreads();                                  // partials ready

      // ---- z update by warp 0 lanes 0..15 ----
      const unsigned en = ec + 1;
      if (tid < RPC) {
        float s_m = part_m[tid] + part_m[16 + tid];
        if (first) dr[tid] = part_w[tid] + part_w[16 + tid] + ul[tid];
        float z = zl[tid], f = fzs[rowb + tid];
        float dz = (z - dr[tid]) - (1.f - f * f) * (gl[tid] - s_m);
        z -= lr * dz; zl[tid] = z;
        g_fz[en & 1][rowb + tid] = tanhf(z);
        __syncwarp(0x0000ffffu);
        if (tid == 0) {
          __threadfence();                              // release publish
          atomicAdd(&g_bar, 1u);
          const unsigned tgt = en * (unsigned)NCTA;
          while (*((volatile unsigned*)&g_bar) < tgt) { __nanosleep(20); }
          __threadfence();                              // acquire
        }
      }
      ec = en;
      __syncthreads();                                  // all see barrier passed

      // ---- reload updated fz into SMEM (skip only at the very end) ----
      if (!(t == SEQ - 1 && k == n_it - 1)) {
        const float4* s = (const float4*)(g_fz[ec & 1]);
        float4* d4 = (float4*)fzs;
        d4[tid]       = __ldcg(s + tid);
        d4[tid + 256] = __ldcg(s + tid + 256);
        __syncthreads();
      }
    }

    // outputs: zs[:,t] (row-major LATENT x SEQ) and z_projs (drive) as [t][l]
    if (tid < RPC) {
      zs_out[(size_t)(rowb + tid) * SEQ + t] = zl[tid];
      g_zpt[(size_t)t * LATENT + rowb + tid] = dr[tid];
    }
  }
}

// ---------------- launch ----------------
extern "C" void kernel_launch(void* const* d_in, const int* in_sizes, int n_in,
                              void* d_out, int out_size)
{
  const float* inputs   = (const float*)d_in[0];  // (OBS,  SEQ)
  const float* controls = (const float*)d_in[1];  // (CTRL, SEQ)
  const float* Wr       = (const float*)d_in[2];  // (LATENT, LATENT)
  const float* Win      = (const float*)d_in[3];  // (LATENT, CTRL)
  const float* Wout     = (const float*)d_in[4];  // (OBS, LATENT)
  const int*   p_it     = (const int*)d_in[5];
  const float* p_lr     = (const float*)d_in[6];

  float* zs   = (float*)d_out;                       // (LATENT, SEQ)
  float* pred = zs + (size_t)LATENT * SEQ;           // (OBS, SEQ)

  float *pM, *pGt, *pUt, *pZpt;
  cudaGetSymbolAddress((void**)&pM,   g_M);
  cudaGetSymbolAddress((void**)&pGt,  g_Gt);
  cudaGetSymbolAddress((void**)&pUt,  g_Ut);
  cudaGetSymbolAddress((void**)&pZpt, g_zpt);

  cudaFuncSetAttribute(seq_kernel, cudaFuncAttributeMaxDynamicSharedMemorySize, SEQ_SMEM);

  dim3 thr(256);
  // M = Wout^T Wout (+ barrier reset in block 0)
  gemm_kernel<false,false,false,false,true><<<dim3(LATENT/64, LATENT/64), thr>>>(Wout, Wout, pM, LATENT, LATENT, OBS);
  // Gt[t][l] = sum_i inputs[i][t] * Wout[i][l]
  gemm_kernel<false,false,false,false,false><<<dim3(LATENT/64, SEQ/64), thr>>>(inputs, Wout, pGt, SEQ, LATENT, OBS);
  // Ut[t][l] = sum_c tanh(controls[c][t]) * Win[l][c]
  gemm_kernel<false,true,true,false,false><<<dim3(LATENT/64, SEQ/64), thr>>>(controls, Win, pUt, SEQ, LATENT, CTRL);

  seq_kernel<<<NCTA, NTHR, SEQ_SMEM>>>(Wr, p_it, p_lr, zs);

  // pred[i][t] = sum_l Wout[i][l] * tanh(zpt[t][l])
  gemm_kernel<true,true,false,true,false><<<dim3(SEQ/64, OBS/64), thr>>>(Wout, pZpt, pred, OBS, SEQ, LATENT);
}

// round 4
// speedup vs baseline: 3.0865x; 1.1995x over previous
#include <cuda_runtime.h>
#include <math.h>

#define LATENT 2048
#define OBS    1024
#define CTRL   512
#define SEQ    4096
#define NCTA   128
#define RPC    16        // latent rows per CTA  (NCTA*RPC == LATENT)
#define NTHR   256

// ---------------- persistent device scratch (no allocations allowed) ----------------
__device__ __align__(16) float g_M  [(size_t)LATENT*LATENT]; // Wout^T Wout
__device__ __align__(16) float g_Gt [(size_t)SEQ*LATENT];    // (Wout^T x_t)   [t][l]
__device__ __align__(16) float g_Ut [(size_t)SEQ*LATENT];    // (Win tanh(u_t))[t][l]
__device__ __align__(16) float g_zpt[(size_t)SEQ*LATENT];    // z_projs (drive)[t][l]
__device__ __align__(16) float g_fz [2][LATENT];             // double-buffered tanh(z)
__device__ unsigned g_bar;                                   // central epoch counter

// ---------------- sync primitives ----------------
__device__ __forceinline__ void red_release_add(unsigned* p, unsigned v) {
  asm volatile("red.release.gpu.global.add.u32 [%0], %1;" :: "l"(p), "r"(v) : "memory");
}
__device__ __forceinline__ unsigned ld_acq(const unsigned* p) {
  unsigned v;
  asm volatile("ld.acquire.gpu.global.u32 %0, [%1];" : "=r"(v) : "l"(p) : "memory");
  return v;
}

// ---------------- generic tiled fp32 GEMM ----------------
// C[Md x Nd] row-major, C[m][n] = sum_k a(k,m)*b(k,n)
//   a(k,m) = TA ? A[m*Kd + k] : A[k*Md + m]    (optionally tanh)
//   b(k,n) = TB ? B[n*Kd + k] : B[k*Nd + n]    (optionally tanh)
// RESET: block (0,0) zeroes barrier counter and fz buffers (graph-replay safety).
template<bool TA, bool TB, bool TANHA, bool TANHB, bool RESET>
__global__ void gemm_kernel(const float* __restrict__ A, const float* __restrict__ B,
                            float* __restrict__ C, int Md, int Nd, int Kd)
{
  if (RESET && blockIdx.x == 0 && blockIdx.y == 0) {
    if (threadIdx.x == 0) g_bar = 0u;
    for (int i = threadIdx.x; i < 2 * LATENT; i += blockDim.x)
      ((float*)g_fz)[i] = 0.f;
  }

  __shared__ float As[16][68];
  __shared__ float Bs[16][68];
  const int tx = threadIdx.x & 15;
  const int ty = threadIdx.x >> 4;
  const int m0 = blockIdx.y * 64;
  const int n0 = blockIdx.x * 64;
  float acc[4][4];
  #pragma unroll
  for (int i = 0; i < 4; i++)
    #pragma unroll
    for (int j = 0; j < 4; j++) acc[i][j] = 0.f;

  for (int k0 = 0; k0 < Kd; k0 += 16) {
    #pragma unroll
    for (int l = 0; l < 4; l++) {
      int i = threadIdx.x + l * 256;
      int kk, mm;
      if (TA) { kk = i & 15; mm = i >> 4; } else { kk = i >> 6; mm = i & 63; }
      float v = TA ? A[(size_t)(m0 + mm) * Kd + (k0 + kk)]
                   : A[(size_t)(k0 + kk) * Md + (m0 + mm)];
      if (TANHA) v = tanhf(v);
      As[kk][mm] = v;
      int kk2, nn;
      if (TB) { kk2 = i & 15; nn = i >> 4; } else { kk2 = i >> 6; nn = i & 63; }
      float w = TB ? B[(size_t)(n0 + nn) * Kd + (k0 + kk2)]
                   : B[(size_t)(k0 + kk2) * Nd + (n0 + nn)];
      if (TANHB) w = tanhf(w);
      Bs[kk2][nn] = w;
    }
    __syncthreads();
    #pragma unroll
    for (int kk = 0; kk < 16; kk++) {
      float a[4], bb[4];
      #pragma unroll
      for (int i = 0; i < 4; i++) a[i]  = As[kk][ty * 4 + i];
      #pragma unroll
      for (int j = 0; j < 4; j++) bb[j] = Bs[kk][tx * 4 + j];
      #pragma unroll
      for (int i = 0; i < 4; i++)
        #pragma unroll
        for (int j = 0; j < 4; j++)
          acc[i][j] += a[i] * bb[j];
    }
    __syncthreads();
  }
  #pragma unroll
  for (int i = 0; i < 4; i++)
    #pragma unroll
    for (int j = 0; j < 4; j++)
      C[(size_t)(m0 + ty * 4 + i) * Nd + (n0 + tx * 4 + j)] = acc[i][j];
}

// ---------------- persistent sequential kernel ----------------
__device__ __forceinline__ void bfly4(float& a0, float& a1, float& a2, float& a3) {
  #pragma unroll
  for (int s = 16; s; s >>= 1) {
    a0 += __shfl_xor_sync(0xffffffffu, a0, s);
    a1 += __shfl_xor_sync(0xffffffffu, a1, s);
    a2 += __shfl_xor_sync(0xffffffffu, a2, s);
    a3 += __shfl_xor_sync(0xffffffffu, a3, s);
  }
}
__device__ __forceinline__ float dot4(float4 a, float4 b) {
  return a.x * b.x + a.y * b.y + a.z * b.z + a.w * b.w;
}

#define SEQ_SMEM ((32768 + 64) * 4)   // M slice + 2x16+... partials = 131328 bytes

__global__ void __launch_bounds__(NTHR, 1)
seq_kernel(const float* __restrict__ Wr,
           const int* __restrict__ p_it, const float* __restrict__ p_lr,
           float* __restrict__ zs_out)
{
  extern __shared__ float sm[];
  float* Ms     = sm;               // 16 x 2048 : this CTA's slice of M
  float* part_m = Ms + 32768;       // 32 : [h*16 + row] partials (M pass)
  float* part_w = part_m + 32;      // 32 : partials (Wr pass, k==0 only)

  const int b    = blockIdx.x;
  const int tid  = threadIdx.x;
  const int w    = tid >> 5, lane = tid & 31;
  const int g    = w >> 1;          // row group: rows 4g..4g+3
  const int h    = w & 1;           // K half: [1024h, 1024h+1024)
  const int rowb = b * RPC;

  // stage M slice into SMEM once
  {
    const float4* src = (const float4*)(g_M + (size_t)rowb * LATENT);
    float4* dst = (float4*)Ms;
    #pragma unroll 4
    for (int i = tid; i < RPC * LATENT / 4; i += NTHR) dst[i] = src[i];
  }

  int n_it = p_it[0];
  if (n_it <= 0 || n_it > 1000000) n_it = (int)(((const long long*)p_it)[0]);
  float lr = p_lr[0];
  if (!(lr > 1e-8f && lr < 16.f)) lr = (float)(((const double*)p_lr)[0]);

  // per-warp base pointers (float4 units; row stride = 512 float4)
  const float4* Ms4 = (const float4*)Ms + (4 * g) * 512 + h * 256;
  const float4* Wr4 = (const float4*)Wr + ((size_t)(rowb + 4 * g)) * 512 + h * 256;

  // per-row update state lives in registers of threads 0..15 (same thread every epoch)
  float z_own = 0.f, f_own = 0.f, drv = 0.f, g_r = 0.f, u_r = 0.f;

  unsigned ec = 0;                  // completed epochs; g_fz[ec&1] = current fz state
  __syncthreads();

  for (int t = 0; t < SEQ; t++) {
    if (tid < RPC) {                // latency hidden under the k=0 matvec below
      g_r = __ldg(&g_Gt[(size_t)t * LATENT + rowb + tid]);
      u_r = __ldg(&g_Ut[(size_t)t * LATENT + rowb + tid]);
    }

    for (int k = 0; k < n_it; k++) {
      // ---- fz read: straight from L2 (coherent buffer), 8 loads in flight ----
      const float4* fz4 = (const float4*)(g_fz[ec & 1]) + h * 256;
      float4 f[8];
      #pragma unroll
      for (int i = 0; i < 8; i++) f[i] = __ldcg(fz4 + i * 32 + lane);

      float a0 = 0.f, a1 = 0.f, a2 = 0.f, a3 = 0.f;
      if (k == 0) {                 // fused drive pass: Wr rows from L2
        float w0 = 0.f, w1 = 0.f, w2 = 0.f, w3 = 0.f;
        #pragma unroll
        for (int i = 0; i < 8; i++) {
          const int o = i * 32 + lane;
          a0 += dot4(Ms4[o], f[i]);
          a1 += dot4(Ms4[o + 512], f[i]);
          a2 += dot4(Ms4[o + 1024], f[i]);
          a3 += dot4(Ms4[o + 1536], f[i]);
          w0 += dot4(__ldg(Wr4 + o), f[i]);
          w1 += dot4(__ldg(Wr4 + o + 512), f[i]);
          w2 += dot4(__ldg(Wr4 + o + 1024), f[i]);
          w3 += dot4(__ldg(Wr4 + o + 1536), f[i]);
        }
        bfly4(w0, w1, w2, w3);
        if (lane < 4) {
          float v = (lane == 0) ? w0 : (lane == 1) ? w1 : (lane == 2) ? w2 : w3;
          part_w[h * 16 + 4 * g + lane] = v;
        }
      } else {
        #pragma unroll
        for (int i = 0; i < 8; i++) {
          const int o = i * 32 + lane;
          a0 += dot4(Ms4[o], f[i]);
          a1 += dot4(Ms4[o + 512], f[i]);
          a2 += dot4(Ms4[o + 1024], f[i]);
          a3 += dot4(Ms4[o + 1536], f[i]);
        }
      }
      bfly4(a0, a1, a2, a3);
      if (lane < 4) {
        float v = (lane == 0) ? a0 : (lane == 1) ? a1 : (lane == 2) ? a2 : a3;
        part_m[h * 16 + 4 * g + lane] = v;
      }
      __syncthreads();                                  // partials ready

      // ---- z update: 16 register-resident rows, publish, arrive ----
      if (tid < RPC) {
        float s_m = part_m[tid] + part_m[16 + tid];
        if (k == 0) drv = part_w[tid] + part_w[16 + tid] + u_r;
        float dz = (z_own - drv) - (1.f - f_own * f_own) * (g_r - s_m);
        z_own -= lr * dz;
        f_own = tanhf(z_own);
        g_fz[(ec + 1) & 1][rowb + tid] = f_own;         // 64B coalesced publish
        __syncwarp(0x0000ffffu);
        if (tid == 0) red_release_add(&g_bar, 1u);      // fz stores ordered before arrive
      }
      ec++;
      // ---- wait: single tight poller (acquire), others park at the CTA barrier ----
      if (tid == 0 && !(t == SEQ - 1 && k == n_it - 1)) {
        const unsigned tgt = ec * (unsigned)NCTA;
        while (ld_acq(&g_bar) < tgt) { }
      }
      __syncthreads();
    }

    // outputs: zs[:,t] (row-major LATENT x SEQ) and z_projs (drive) as [t][l]
    if (tid < RPC) {
      zs_out[(size_t)(rowb + tid) * SEQ + t] = z_own;
      g_zpt[(size_t)t * LATENT + rowb + tid] = drv;
    }
  }
}

// ---------------- launch ----------------
extern "C" void kernel_launch(void* const* d_in, const int* in_sizes, int n_in,
                              void* d_out, int out_size)
{
  const float* inputs   = (const float*)d_in[0];  // (OBS,  SEQ)
  const float* controls = (const float*)d_in[1];  // (CTRL, SEQ)
  const float* Wr       = (const float*)d_in[2];  // (LATENT, LATENT)
  const float* Win      = (const float*)d_in[3];  // (LATENT, CTRL)
  const float* Wout     = (const float*)d_in[4];  // (OBS, LATENT)
  const int*   p_it     = (const int*)d_in[5];
  const float* p_lr     = (const float*)d_in[6];

  float* zs   = (float*)d_out;                       // (LATENT, SEQ)
  float* pred = zs + (size_t)LATENT * SEQ;           // (OBS, SEQ)

  float *pM, *pGt, *pUt, *pZpt;
  cudaGetSymbolAddress((void**)&pM,   g_M);
  cudaGetSymbolAddress((void**)&pGt,  g_Gt);
  cudaGetSymbolAddress((void**)&pUt,  g_Ut);
  cudaGetSymbolAddress((void**)&pZpt, g_zpt);

  cudaFuncSetAttribute(seq_kernel, cudaFuncAttributeMaxDynamicSharedMemorySize, SEQ_SMEM);

  dim3 thr(256);
  // M = Wout^T Wout (+ barrier/fz reset in block 0)
  gemm_kernel<false,false,false,false,true><<<dim3(LATENT/64, LATENT/64), thr>>>(Wout, Wout, pM, LATENT, LATENT, OBS);
  // Gt[t][l] = sum_i inputs[i][t] * Wout[i][l]
  gemm_kernel<false,false,false,false,false><<<dim3(LATENT/64, SEQ/64), thr>>>(inputs, Wout, pGt, SEQ, LATENT, OBS);
  // Ut[t][l] = sum_c tanh(controls[c][t]) * Win[l][c]
  gemm_kernel<false,true,true,false,false><<<dim3(LATENT/64, SEQ/64), thr>>>(controls, Win, pUt, SEQ, LATENT, CTRL);

  seq_kernel<<<NCTA, NTHR, SEQ_SMEM>>>(Wr, p_it, p_lr, zs);

  // pred[i][t] = sum_l Wout[i][l] * tanh(zpt[t][l])
  gemm_kernel<true,true,false,true,false><<<dim3(SEQ/64, OBS/64), thr>>>(Wout, pZpt, pred, OBS, SEQ, LATENT);
}